// round 16
// baseline (speedup 1.0000x reference)
#include <cuda_runtime.h>
#include <cuda_bf16.h>
#include <cstdint>

// DLRM dot-interaction via BF16 tensor cores, 3-term split.
// One sample per 128-thread CTA. Load phase splits fp32 -> bf16 hi/lo PLANES in
// smem (split off the critical path). Each warp owns whole output tiles over the
// FULL k=128 (w0:{(0,0),(0,1)} w1:{(0,2),(0,3)} w2:{(1,2)} w3:{(1,3)}), so there
// is no split-k reduction, no exchange buffer, and exactly ONE barrier.
// A-fragments alias B-fragments (SYRK symmetry): a(mt) = interleave(b(2mt), b(2mt+1)).
// 3 mmas/position: al*bh + ah*bl + ah*bh; dropped al*bl ~ 2^-16.

constexpr int Bt    = 16384;
constexpr int NE    = 26;
constexpr int D     = 128;
constexpr int N     = 27;
constexpr int NPAIR = N * (N - 1) / 2;     // 351
constexpr int STRH  = 136;                 // shorts per plane row (272 B)
constexpr int NTHR  = 128;
constexpr int NF4   = 864;                 // float4 per sample (27 rows x 32)

__device__ __forceinline__ void mma_bf16(float* c,
    uint32_t a0, uint32_t a1, uint32_t a2, uint32_t a3,
    uint32_t b0, uint32_t b1)
{
    asm volatile(
        "mma.sync.aligned.m16n8k16.row.col.f32.bf16.bf16.f32 "
        "{%0,%1,%2,%3}, {%4,%5,%6,%7}, {%8,%9}, {%0,%1,%2,%3};"
        : "+f"(c[0]), "+f"(c[1]), "+f"(c[2]), "+f"(c[3])
        : "r"(a0), "r"(a1), "r"(a2), "r"(a3), "r"(b0), "r"(b1));
}

__global__ void __launch_bounds__(NTHR)
dot_interaction_kernel(const float* __restrict__ dense,
                       const float* __restrict__ embs,
                       float* __restrict__ out)
{
    __shared__ uint16_t Shi[32 * STRH];              // 8704 B
    __shared__ uint16_t Slo[32 * STRH];              // 8704 B

    const int tid  = threadIdx.x;
    const int w    = tid >> 5;                       // warp id: tile owner
    const int lane = tid & 31;
    const int g    = lane >> 2;
    const int t4   = lane & 3;
    const int sample = blockIdx.x;

    // ---- Load + split phase: fp32 gmem -> bf16 hi/lo planes ----
    const float4* d4 = reinterpret_cast<const float4*>(dense + (size_t)sample * D);
    const float4* e4 = reinterpret_cast<const float4*>(embs + (size_t)sample * NE * D);

    #pragma unroll
    for (int i = 0; i < 7; i++) {                    // 864 f4 over 128 threads
        const int idx = tid + i * NTHR;
        if (idx < NF4) {
            const int row = idx >> 5, c0 = (idx & 31) * 4;   // shorts index
            const float4 v = (idx < 32) ? d4[idx] : e4[idx - 32];
            const uint32_t bx = __float_as_uint(v.x), by = __float_as_uint(v.y);
            const uint32_t bz = __float_as_uint(v.z), bw = __float_as_uint(v.w);
            const uint32_t h0 = __byte_perm(bx, by, 0x7632);
            const uint32_t h1 = __byte_perm(bz, bw, 0x7632);
            __nv_bfloat162 l0 = __floats2bfloat162_rn(
                v.x - __uint_as_float(bx & 0xFFFF0000u),
                v.y - __uint_as_float(by & 0xFFFF0000u));
            __nv_bfloat162 l1 = __floats2bfloat162_rn(
                v.z - __uint_as_float(bz & 0xFFFF0000u),
                v.w - __uint_as_float(bw & 0xFFFF0000u));
            *reinterpret_cast<uint2*>(&Shi[row * STRH + c0]) =
                make_uint2(h0, h1);
            *reinterpret_cast<uint2*>(&Slo[row * STRH + c0]) =
                make_uint2(*reinterpret_cast<uint32_t*>(&l0),
                           *reinterpret_cast<uint32_t*>(&l1));
        }
    }
    // Zero pad rows 27..31 of both planes (defensive; outputs there are filtered)
    for (int i = tid; i < 5 * (STRH / 2); i += NTHR) {
        reinterpret_cast<uint32_t*>(&Shi[27 * STRH])[i] = 0u;
        reinterpret_cast<uint32_t*>(&Slo[27 * STRH])[i] = 0u;
    }
    __syncthreads();                                 // the ONLY barrier

    // ---- Compute: warp-owned tiles over full k ----
    auto ldfrag = [&](int n, int kc, uint32_t* h, uint32_t* l) {
        h[0] = *reinterpret_cast<const uint32_t*>(&Shi[n * STRH + kc    ]);
        h[1] = *reinterpret_cast<const uint32_t*>(&Shi[n * STRH + kc + 8]);
        l[0] = *reinterpret_cast<const uint32_t*>(&Slo[n * STRH + kc    ]);
        l[1] = *reinterpret_cast<const uint32_t*>(&Slo[n * STRH + kc + 8]);
    };
    // 3-term mma: A composed of frag pair (p, q) = rows (2mt, 2mt+1) octs; B = frag n
    auto mma3 = [&](float* c, const uint32_t* hp, const uint32_t* hq,
                               const uint32_t* lp, const uint32_t* lq,
                               const uint32_t* bhn, const uint32_t* bln) {
        mma_bf16(c, lp[0], lq[0], lp[1], lq[1], bhn[0], bhn[1]);
        mma_bf16(c, hp[0], hq[0], hp[1], hq[1], bln[0], bln[1]);
        mma_bf16(c, hp[0], hq[0], hp[1], hq[1], bhn[0], bhn[1]);
    };

    float accA[4] = {0.f, 0.f, 0.f, 0.f};
    float accB[4] = {0.f, 0.f, 0.f, 0.f};

    if (w == 0) {                                    // tiles (0,0),(0,1): frags b0,b1
        #pragma unroll
        for (int kt = 0; kt < 8; kt++) {
            const int kc = kt * 16 + 2 * t4;
            uint32_t h0[2], l0[2], h1[2], l1[2];
            ldfrag(g,     kc, h0, l0);
            ldfrag(8 + g, kc, h1, l1);
            mma3(accA, h0, h1, l0, l1, h0, l0);      // B = b0
            mma3(accB, h0, h1, l0, l1, h1, l1);      // B = b1
        }
    } else if (w == 1) {                             // tiles (0,2),(0,3): frags b0..b3
        #pragma unroll
        for (int kt = 0; kt < 8; kt++) {
            const int kc = kt * 16 + 2 * t4;
            uint32_t h0[2], l0[2], h1[2], l1[2], h2[2], l2[2], h3[2], l3[2];
            ldfrag(g,      kc, h0, l0);
            ldfrag(8 + g,  kc, h1, l1);
            ldfrag(16 + g, kc, h2, l2);
            ldfrag(24 + g, kc, h3, l3);
            mma3(accA, h0, h1, l0, l1, h2, l2);      // B = b2
            mma3(accB, h0, h1, l0, l1, h3, l3);      // B = b3
        }
    } else {                                         // w2: (1,2); w3: (1,3): frags b2,b3
        #pragma unroll
        for (int kt = 0; kt < 8; kt++) {
            const int kc = kt * 16 + 2 * t4;
            uint32_t h2[2], l2[2], h3[2], l3[2];
            ldfrag(16 + g, kc, h2, l2);
            ldfrag(24 + g, kc, h3, l3);
            if (w == 2) mma3(accA, h2, h3, l2, l3, h2, l2);  // B = b2
            else        mma3(accA, h2, h3, l2, l3, h3, l3);  // B = b3
        }
    }

    // ---- Epilogue: direct store of owned tiles (no reduction, no barrier) ----
    // tile table: e -> (mt, nt); w0: e 0,1; w1: e 2,3; w2: e 4; w3: e 5.
    constexpr int MT[6] = {0, 0, 0, 0, 1, 1};
    constexpr int NT[6] = {0, 1, 2, 3, 2, 3};
    float* orow = out + (size_t)sample * NPAIR;

    auto store_tile = [&](int e, const float* acc) {
        #pragma unroll
        for (int c = 0; c < 4; c++) {
            const int i = MT[e] * 16 + g + ((c & 2) ? 8 : 0);
            const int j = NT[e] * 8 + 2 * t4 + (c & 1);
            if (i < j && j < N)
                orow[i * (2 * N - 1 - i) / 2 + (j - i - 1)] = acc[c];
        }
    };

    if (w == 0)      { store_tile(0, accA); store_tile(1, accB); }
    else if (w == 1) { store_tile(2, accA); store_tile(3, accB); }
    else if (w == 2) { store_tile(4, accA); }
    else             { store_tile(5, accA); }
}

extern "C" void kernel_launch(void* const* d_in, const int* in_sizes, int n_in,
                              void* d_out, int out_size)
{
    const float* dense = (const float*)d_in[0];
    const float* embs  = (const float*)d_in[1];
    float* out = (float*)d_out;
    dot_interaction_kernel<<<Bt, NTHR>>>(dense, embs, out);
}